// round 14
// baseline (speedup 1.0000x reference)
#include <cuda_runtime.h>
#include <cuda_fp16.h>
#include <math.h>
#include <stdint.h>

#define N_NODE   512
#define N_GRAPH  16
#define EMBED    768
#define NHEAD    12
#define HDIM     64
#define M_ROWS   (N_NODE * N_GRAPH)   // 8192

// Scratch (device globals — no allocation allowed)
__device__ __half g_qh[M_ROWS * EMBED];
__device__ __half g_kh[M_ROWS * EMBED];
__device__ __half g_vh[M_ROWS * EMBED];
__device__ __half g_ah[M_ROWS * EMBED];        // attn output (half)
__device__ __half g_xh[M_ROWS * EMBED];        // x converted to half
__device__ __half g_wqh[EMBED * EMBED];
__device__ __half g_wkh[EMBED * EMBED];
__device__ __half g_wvh[EMBED * EMBED];
__device__ __half g_woh[EMBED * EMBED];

// ---------------------------------------------------------------------------
// helpers
// ---------------------------------------------------------------------------
__device__ __forceinline__ void mma_f16(float d[4], const unsigned a[4], const unsigned b[2]) {
    asm volatile(
        "mma.sync.aligned.m16n8k16.row.col.f32.f16.f16.f32 "
        "{%0,%1,%2,%3},{%4,%5,%6,%7},{%8,%9},{%0,%1,%2,%3};"
        : "+f"(d[0]), "+f"(d[1]), "+f"(d[2]), "+f"(d[3])
        : "r"(a[0]), "r"(a[1]), "r"(a[2]), "r"(a[3]), "r"(b[0]), "r"(b[1]));
}

__device__ __forceinline__ void ldmatrix_x4(unsigned r[4], uint32_t addr) {
    asm volatile("ldmatrix.sync.aligned.m8n8.x4.shared.b16 {%0,%1,%2,%3}, [%4];"
                 : "=r"(r[0]), "=r"(r[1]), "=r"(r[2]), "=r"(r[3]) : "r"(addr));
}

__device__ __forceinline__ void ldmatrix_x4_t(unsigned r[4], uint32_t addr) {
    asm volatile("ldmatrix.sync.aligned.m8n8.x4.trans.shared.b16 {%0,%1,%2,%3}, [%4];"
                 : "=r"(r[0]), "=r"(r[1]), "=r"(r[2]), "=r"(r[3]) : "r"(addr));
}

__device__ __forceinline__ void cp_async16(uint32_t saddr, const void* gptr) {
    asm volatile("cp.async.cg.shared.global [%0], [%1], 16;" :: "r"(saddr), "l"(gptr));
}
#define CP_COMMIT() asm volatile("cp.async.commit_group;")
#define CP_WAIT(n)  asm volatile("cp.async.wait_group %0;" :: "n"(n))

__device__ __forceinline__ uint32_t smem_u32(const void* p) {
    return (uint32_t)__cvta_generic_to_shared(p);
}

__device__ __forceinline__ unsigned packh2(float a, float b) {
    __half2 h = __floats2half2_rn(a, b);
    return *(unsigned*)&h;
}

// ===========================================================================
// fp16 GEMM (round-12 proven body): 128x128 tile, BK=64, 8 warps, 3-stage,
// single barrier per chunk. Output float (Cf) or half (Ch).
// ===========================================================================
#define GEMM_SMEM_BYTES 98304

__device__ __forceinline__ void gemm_h_body(
    const __half* __restrict__ A, const __half* __restrict__ W,
    const float* __restrict__ bias, float* __restrict__ Cf, __half* __restrict__ Ch,
    float alpha, int bm, int bn, char* smem)
{
    const uint32_t sb = smem_u32(smem);
    const int tid  = threadIdx.x;
    const int lane = tid & 31;
    const int warp = tid >> 5;
    const int wm = warp & 3;
    const int wn = warp >> 2;

    float acc[2][8][4] = {};

    const __half* Abase = A + (size_t)bm * EMBED;
    const __half* Wbase = W + (size_t)bn * EMBED;

    auto stage = [&](int c) {
        uint32_t buf = sb + (uint32_t)(c % 3) * 32768;
        const __half* ga = Abase + c * 64;
        const __half* gb = Wbase + c * 64;
#pragma unroll
        for (int l = 0; l < 4; l++) {
            int idx = tid + l * 256;
            int r = idx >> 3;
            int s = idx & 7;
            uint32_t off = (uint32_t)(r * 128 + ((s ^ (r & 7)) << 4));
            cp_async16(buf + off,         ga + (size_t)r * EMBED + s * 8);
            cp_async16(buf + 16384 + off, gb + (size_t)r * EMBED + s * 8);
        }
        CP_COMMIT();
    };

    const int r8  = lane & 7;
    const int sub = lane >> 3;

    auto compute = [&](int buf) {
        uint32_t ab = sb + (uint32_t)buf * 32768;
        uint32_t bb = ab + 16384;
#pragma unroll
        for (int ks = 0; ks < 4; ks++) {
            unsigned af[2][4];
#pragma unroll
            for (int mt = 0; mt < 2; mt++) {
                int row = wm * 32 + mt * 16 + ((sub & 1) << 3) + r8;
                int cs  = ks * 2 + (sub >> 1);
                ldmatrix_x4(af[mt], ab + row * 128 + (((cs ^ (row & 7))) << 4));
            }
#pragma unroll
            for (int np = 0; np < 4; np++) {
                int row = wn * 64 + np * 16 + ((sub >> 1) << 3) + r8;
                int cs  = ks * 2 + (sub & 1);
                unsigned bf[4];
                ldmatrix_x4(bf, bb + row * 128 + (((cs ^ (row & 7))) << 4));
                unsigned b0[2] = {bf[0], bf[1]};
                unsigned b1[2] = {bf[2], bf[3]};
#pragma unroll
                for (int mt = 0; mt < 2; mt++) {
                    mma_f16(acc[mt][np * 2 + 0], af[mt], b0);
                    mma_f16(acc[mt][np * 2 + 1], af[mt], b1);
                }
            }
        }
    };

    stage(0);
    stage(1);
#pragma unroll 1
    for (int c = 0; c < 12; c++) {
        if (c < 11) { CP_WAIT(1); } else { CP_WAIT(0); }
        __syncthreads();
        if (c + 2 < 12) stage(c + 2);
        compute(c % 3);
    }

    const int g  = lane >> 2;
    const int tg = lane & 3;
#pragma unroll
    for (int mt = 0; mt < 2; mt++) {
        int m0 = bm + wm * 32 + mt * 16 + g;
#pragma unroll
        for (int nt = 0; nt < 8; nt++) {
            int n0 = bn + wn * 64 + nt * 8 + tg * 2;
            float2 bi = *(const float2*)&bias[n0];
            float o00 = alpha * (acc[mt][nt][0] + bi.x);
            float o01 = alpha * (acc[mt][nt][1] + bi.y);
            float o10 = alpha * (acc[mt][nt][2] + bi.x);
            float o11 = alpha * (acc[mt][nt][3] + bi.y);
            if (Ch) {
                *(__half2*)&Ch[(size_t)m0 * EMBED + n0] = __floats2half2_rn(o00, o01);
                *(__half2*)&Ch[(size_t)(m0 + 8) * EMBED + n0] = __floats2half2_rn(o10, o11);
            } else {
                *(float2*)&Cf[(size_t)m0 * EMBED + n0] = make_float2(o00, o01);
                *(float2*)&Cf[(size_t)(m0 + 8) * EMBED + n0] = make_float2(o10, o11);
            }
        }
    }
}

__global__ __launch_bounds__(256, 2) void gemm_qkv_h(
    const __half* __restrict__ x,
    const __half* __restrict__ wq, const __half* __restrict__ wk, const __half* __restrict__ wv,
    const float* __restrict__ bq, const float* __restrict__ bk, const float* __restrict__ bv,
    __half* __restrict__ qo, __half* __restrict__ ko, __half* __restrict__ vo)
{
    extern __shared__ char gsm[];
    int sel = blockIdx.x / 6;
    int bn  = (blockIdx.x % 6) * 128;
    int bm  = blockIdx.y * 128;
    const __half* W   = (sel == 0) ? wq : (sel == 1) ? wk : wv;
    const float* bias = (sel == 0) ? bq : (sel == 1) ? bk : bv;
    __half* C         = (sel == 0) ? qo : (sel == 1) ? ko : vo;
    float alpha       = (sel == 0) ? 0.125f : 1.0f;
    gemm_h_body(x, W, bias, nullptr, C, alpha, bm, bn, gsm);
}

__global__ __launch_bounds__(256, 2) void gemm_out_h(
    const __half* __restrict__ A, const __half* __restrict__ W,
    const float* __restrict__ bias, float* __restrict__ C)
{
    extern __shared__ char gsm[];
    gemm_h_body(A, W, bias, C, nullptr, 1.0f, blockIdx.y * 128, blockIdx.x * 128, gsm);
}

// ---------------------------------------------------------------------------
// prep: convert x and the 4 weight matrices to half
// ---------------------------------------------------------------------------
#define NX4 (M_ROWS * EMBED / 4)
#define NW4 (EMBED * EMBED / 4)

__global__ __launch_bounds__(256) void prep_h(
    const float4* __restrict__ x,
    const float4* __restrict__ wq, const float4* __restrict__ wk,
    const float4* __restrict__ wv, const float4* __restrict__ wo,
    uint2* __restrict__ xh,
    uint2* __restrict__ wqh, uint2* __restrict__ wkh,
    uint2* __restrict__ wvh, uint2* __restrict__ woh)
{
    int i = blockIdx.x * 256 + threadIdx.x;
    auto cv = [](float4 t) {
        __half2 h0 = __floats2half2_rn(t.x, t.y);
        __half2 h1 = __floats2half2_rn(t.z, t.w);
        uint2 o;
        o.x = *(unsigned*)&h0;
        o.y = *(unsigned*)&h1;
        return o;
    };
    if (i < NX4) xh[i] = cv(x[i]);
    if (i < NW4) {
        wqh[i] = cv(wq[i]);
        wkh[i] = cv(wk[i]);
        wvh[i] = cv(wv[i]);
        woh[i] = cv(wo[i]);
    }
}

// ===========================================================================
// Streaming fused attention — 4 warps, warp tile 32q x 32k (crossbar relief).
// Block = (128 q rows, head b), 128 threads; warp w owns q rows [w*32, w*32+32).
// K/V fragments shared by 4 warps instead of 8 -> K/V LDSM traffic halves.
// 32-key chunks; K/V/bias triple-buffered; per chunk:
//   WAIT -> sync -> stage(ch+2) -> compute(ch)
// Q ldmatrix'd once into registers. P stays in registers (FA2 trick).
// SMEM: K 3x4K + V 3x4K + bias 3x18K = 78K -> 2 CTAs/SM.
// ===========================================================================
#define CH 32
#define NCH (N_NODE / CH)          // 16
#define KB_OFF    0
#define VB_OFF    (3 * 4096)                   // 12288
#define BIASB_OFF (2 * 3 * 4096)               // 24576
#define BIAS_LDB  144              // bytes per bias row (36 floats)
#define BIAS_BYTES (128 * BIAS_LDB)            // 18432
#define ATTN_SMEM_BYTES (BIASB_OFF + 3 * BIAS_BYTES)   // 79872
#define ATHREADS 128

__global__ __launch_bounds__(ATHREADS, 2) void attn_h(
    const __half* __restrict__ q, const __half* __restrict__ k,
    const __half* __restrict__ v, const float* __restrict__ bias,
    const float* __restrict__ amask, const unsigned char* __restrict__ pad,
    __half* __restrict__ outh)
{
    extern __shared__ char asm_[];
    const uint32_t sb = smem_u32(asm_);

    const int b = blockIdx.y;
    const int graph = b / NHEAD;
    const int head  = b % NHEAD;
    const int q0 = blockIdx.x * 128;
    const int tid  = threadIdx.x;
    const int lane = tid & 31;
    const int w    = tid >> 5;      // 0..3
    const int r8   = lane & 7;
    const int sub  = lane >> 3;
    const int g    = lane >> 2;
    const int tg   = lane & 3;

    const int qrow = w * 32 + g;    // base q row for qt=0 fragment

    const float* bias_gbase = bias + ((size_t)b * N_NODE + q0) * N_NODE;

    // ---- stage K/V/bias for chunk ch into buffer ch%3 (one commit group) ----
    auto stage = [&](int ch) {
        uint32_t buf = (uint32_t)(ch % 3);
#pragma unroll
        for (int l = 0; l < 2; l++) {
            int idx = tid + l * ATHREADS;    // 0..255 (32 rows x 8 segs)
            int r = idx >> 3, s = idx & 7;
            uint32_t off = (uint32_t)(r * 128 + ((s ^ (r & 7)) << 4));
            const __half* gk = k + ((size_t)(ch * CH + r) * N_GRAPH + graph) * EMBED + head * HDIM + s * 8;
            const __half* gv = v + ((size_t)(ch * CH + r) * N_GRAPH + graph) * EMBED + head * HDIM + s * 8;
            cp_async16(sb + KB_OFF + buf * 4096 + off, gk);
            cp_async16(sb + VB_OFF + buf * 4096 + off, gv);
        }
#pragma unroll
        for (int l = 0; l < 8; l++) {
            int idx = tid + l * ATHREADS;    // 0..1023 (128 rows x 8 segs)
            int r = idx >> 3, s = idx & 7;
            uint32_t dst = sb + BIASB_OFF + buf * BIAS_BYTES + (uint32_t)(r * BIAS_LDB + s * 16);
            const float* src = bias_gbase + (size_t)r * N_NODE + ch * CH + s * 4;
            cp_async16(dst, src);
        }
        CP_COMMIT();
    };

    // ---- Q fragments: stage once into bias area, ldmatrix into registers ----
    unsigned afq[2][4][4];   // [qt][ks][reg]
    {
#pragma unroll
        for (int l = 0; l < 8; l++) {
            int idx = tid + l * ATHREADS;    // 0..1023 (128 rows x 8 segs)
            int r = idx >> 3, s = idx & 7;
            uint32_t off = (uint32_t)(r * 128 + ((s ^ (r & 7)) << 4));
            const __half* src = q + ((size_t)(q0 + r) * N_GRAPH + graph) * EMBED + head * HDIM + s * 8;
            cp_async16(sb + BIASB_OFF + off, src);
        }
        CP_COMMIT();
        CP_WAIT(0);
        __syncthreads();
#pragma unroll
        for (int qt = 0; qt < 2; qt++) {
#pragma unroll
            for (int ks = 0; ks < 4; ks++) {
                int row = w * 32 + qt * 16 + ((sub & 1) << 3) + r8;
                int cs  = ks * 2 + (sub >> 1);
                ldmatrix_x4(afq[qt][ks], sb + BIASB_OFF + row * 128 + (((cs ^ (row & 7))) << 4));
            }
        }
        __syncthreads();   // Q temp reads complete before bias staging overwrites
    }
    stage(0);
    stage(1);

    float psum0[2] = {0.f, 0.f};   // rows qrow+qt*16
    float psum8[2] = {0.f, 0.f};   // rows qrow+qt*16+8
    float oacc[2][8][4] = {};

#pragma unroll 1
    for (int ch = 0; ch < NCH; ch++) {
        const int buf = ch % 3;

        // ---- prefetch mask + pad (independent of staged data) ----
        float2 mk0[2][4], mk1[2][4];
        uchar2 pd[4];
        {
            const uchar2* pp = (const uchar2*)&pad[graph * N_NODE + ch * CH];
#pragma unroll
            for (int nt = 0; nt < 4; nt++) {
                int kg = ch * CH + nt * 8 + tg * 2;
                pd[nt] = pp[nt * 4 + tg];
#pragma unroll
                for (int qt = 0; qt < 2; qt++) {
                    int qa = q0 + qrow + qt * 16;
                    mk0[qt][nt] = *(const float2*)&amask[(size_t)qa * N_NODE + kg];
                    mk1[qt][nt] = *(const float2*)&amask[(size_t)(qa + 8) * N_NODE + kg];
                }
            }
        }

        if (ch < NCH - 1) { CP_WAIT(1); } else { CP_WAIT(0); }
        __syncthreads();   // chunk ch visible; all warps past compute(ch-1)

        if (ch + 2 < NCH) stage(ch + 2);   // writes buffer (ch-1)%3 — safe

        const uint32_t kbuf = sb + KB_OFF + (uint32_t)buf * 4096;
        const uint32_t vbuf = sb + VB_OFF + (uint32_t)buf * 4096;
        const float* bbuf = (const float*)(asm_ + BIASB_OFF + buf * BIAS_BYTES);

        // ---- S = Q K^T : warp tile 32q x 32k ----
        float sacc[2][4][4] = {};
#pragma unroll
        for (int ks = 0; ks < 4; ks++) {
#pragma unroll
            for (int np = 0; np < 2; np++) {
                int row = np * 16 + ((sub >> 1) << 3) + r8;
                int cs  = ks * 2 + (sub & 1);
                unsigned bf[4];
                ldmatrix_x4(bf, kbuf + row * 128 + (((cs ^ (row & 7))) << 4));
                unsigned b0[2] = {bf[0], bf[1]};
                unsigned b1[2] = {bf[2], bf[3]};
#pragma unroll
                for (int qt = 0; qt < 2; qt++) {
                    mma_f16(sacc[qt][np * 2 + 0], afq[qt][ks], b0);
                    mma_f16(sacc[qt][np * 2 + 1], afq[qt][ks], b1);
                }
            }
        }

        // ---- exp(S + bias + mask) in place ----
#pragma unroll
        for (int qt = 0; qt < 2; qt++) {
            int r0 = qrow + qt * 16;
#pragma unroll
            for (int nt = 0; nt < 4; nt++) {
                float2 bi0 = *(const float2*)&bbuf[r0 * 36 + nt * 8 + tg * 2];
                float2 bi1 = *(const float2*)&bbuf[(r0 + 8) * 36 + nt * 8 + tg * 2];
                bool p0 = pd[nt].x, p1 = pd[nt].y;
                sacc[qt][nt][0] = p0 ? 0.f : __expf(sacc[qt][nt][0] + bi0.x + mk0[qt][nt].x);
                sacc[qt][nt][1] = p1 ? 0.f : __expf(sacc[qt][nt][1] + bi0.y + mk0[qt][nt].y);
                sacc[qt][nt][2] = p0 ? 0.f : __expf(sacc[qt][nt][2] + bi1.x + mk1[qt][nt].x);
                sacc[qt][nt][3] = p1 ? 0.f : __expf(sacc[qt][nt][3] + bi1.y + mk1[qt][nt].y);
                psum0[qt] += sacc[qt][nt][0] + sacc[qt][nt][1];
                psum8[qt] += sacc[qt][nt][2] + sacc[qt][nt][3];
            }
        }

        // ---- O += P V : P packed in registers (FA2) ----
#pragma unroll
        for (int kk = 0; kk < 2; kk++) {
            unsigned pa[2][4];
#pragma unroll
            for (int qt = 0; qt < 2; qt++) {
                pa[qt][0] = packh2(sacc[qt][kk * 2][0], sacc[qt][kk * 2][1]);
                pa[qt][1] = packh2(sacc[qt][kk * 2][2], sacc[qt][kk * 2][3]);
                pa[qt][2] = packh2(sacc[qt][kk * 2 + 1][0], sacc[qt][kk * 2 + 1][1]);
                pa[qt][3] = packh2(sacc[qt][kk * 2 + 1][2], sacc[qt][kk * 2 + 1][3]);
            }
#pragma unroll
            for (int nn = 0; nn < 4; nn++) {
                int row = kk * 16 + ((sub & 1) << 3) + r8;     // key row
                int seg = nn * 2 + (sub >> 1);                 // d segment
                unsigned vf[4];
                ldmatrix_x4_t(vf, vbuf + row * 128 + (((seg ^ (row & 7))) << 4));
                unsigned b0[2] = {vf[0], vf[1]};
                unsigned b1[2] = {vf[2], vf[3]};
#pragma unroll
                for (int qt = 0; qt < 2; qt++) {
                    mma_f16(oacc[qt][nn * 2 + 0], pa[qt], b0);
                    mma_f16(oacc[qt][nn * 2 + 1], pa[qt], b1);
                }
            }
        }
    }

    // ---- normalize + write half (node, graph, embed) ----
#pragma unroll
    for (int qt = 0; qt < 2; qt++) {
        float s0 = psum0[qt], s8 = psum8[qt];
        s0 += __shfl_xor_sync(0xffffffffu, s0, 1);
        s0 += __shfl_xor_sync(0xffffffffu, s0, 2);
        s8 += __shfl_xor_sync(0xffffffffu, s8, 1);
        s8 += __shfl_xor_sync(0xffffffffu, s8, 2);
        float inv0 = 1.0f / s0;
        float inv8 = 1.0f / s8;
        int node = q0 + qrow + qt * 16;
#pragma unroll
        for (int nt = 0; nt < 8; nt++) {
            int d = nt * 8 + tg * 2;
            *(__half2*)&outh[((size_t)node * N_GRAPH + graph) * EMBED + head * HDIM + d] =
                __floats2half2_rn(oacc[qt][nt][0] * inv0, oacc[qt][nt][1] * inv0);
            *(__half2*)&outh[((size_t)(node + 8) * N_GRAPH + graph) * EMBED + head * HDIM + d] =
                __floats2half2_rn(oacc[qt][nt][2] * inv8, oacc[qt][nt][3] * inv8);
        }
    }
}

// ---------------------------------------------------------------------------
extern "C" void kernel_launch(void* const* d_in, const int* in_sizes, int n_in,
                              void* d_out, int out_size)
{
    const float* x     = (const float*)d_in[0];
    const float* bias  = (const float*)d_in[1];
    const float* amask = (const float*)d_in[2];
    const unsigned char* pad = (const unsigned char*)d_in[3];
    const float* wq = (const float*)d_in[4];
    const float* bq = (const float*)d_in[5];
    const float* wk = (const float*)d_in[6];
    const float* bk = (const float*)d_in[7];
    const float* wv = (const float*)d_in[8];
    const float* bv = (const float*)d_in[9];
    const float* wo = (const float*)d_in[10];
    const float* bo = (const float*)d_in[11];
    float* out = (float*)d_out;

    __half *qhp, *khp, *vhp, *ahp, *xhp, *wqhp, *wkhp, *wvhp, *wohp;
    cudaGetSymbolAddress((void**)&qhp, g_qh);
    cudaGetSymbolAddress((void**)&khp, g_kh);
    cudaGetSymbolAddress((void**)&vhp, g_vh);
    cudaGetSymbolAddress((void**)&ahp, g_ah);
    cudaGetSymbolAddress((void**)&xhp, g_xh);
    cudaGetSymbolAddress((void**)&wqhp, g_wqh);
    cudaGetSymbolAddress((void**)&wkhp, g_wkh);
    cudaGetSymbolAddress((void**)&wvhp, g_wvh);
    cudaGetSymbolAddress((void**)&wohp, g_woh);

    cudaFuncSetAttribute(gemm_qkv_h, cudaFuncAttributeMaxDynamicSharedMemorySize, GEMM_SMEM_BYTES);
    cudaFuncSetAttribute(gemm_out_h, cudaFuncAttributeMaxDynamicSharedMemorySize, GEMM_SMEM_BYTES);
    cudaFuncSetAttribute(attn_h, cudaFuncAttributeMaxDynamicSharedMemorySize, ATTN_SMEM_BYTES);

    prep_h<<<NX4 / 256, 256>>>(
        (const float4*)x, (const float4*)wq, (const float4*)wk,
        (const float4*)wv, (const float4*)wo,
        (uint2*)xhp, (uint2*)wqhp, (uint2*)wkhp, (uint2*)wvhp, (uint2*)wohp);

    dim3 qkvgrid(18, M_ROWS / 128);   // (18, 64)
    gemm_qkv_h<<<qkvgrid, 256, GEMM_SMEM_BYTES>>>(xhp, wqhp, wkhp, wvhp, bq, bk, bv, qhp, khp, vhp);

    dim3 agrid(N_NODE / 128, N_GRAPH * NHEAD);  // (4, 192)
    attn_h<<<agrid, ATHREADS, ATTN_SMEM_BYTES>>>(qhp, khp, vhp, bias, amask, pad, ahp);

    dim3 ogrid(EMBED / 128, M_ROWS / 128);      // (6, 64)
    gemm_out_h<<<ogrid, 256, GEMM_SMEM_BYTES>>>(ahp, wohp, bo, out);
}

// round 15
// speedup vs baseline: 1.0282x; 1.0282x over previous
#include <cuda_runtime.h>
#include <cuda_fp16.h>
#include <math.h>
#include <stdint.h>

#define N_NODE   512
#define N_GRAPH  16
#define EMBED    768
#define NHEAD    12
#define HDIM     64
#define M_ROWS   (N_NODE * N_GRAPH)   // 8192

// Scratch (device globals — no allocation allowed)
__device__ __half g_qh[M_ROWS * EMBED];
__device__ __half g_kh[M_ROWS * EMBED];
__device__ __half g_vh[M_ROWS * EMBED];
__device__ __half g_ah[M_ROWS * EMBED];        // attn output (half)
__device__ __half g_xh[M_ROWS * EMBED];        // x converted to half
__device__ __half g_wqh[EMBED * EMBED];
__device__ __half g_wkh[EMBED * EMBED];
__device__ __half g_wvh[EMBED * EMBED];
__device__ __half g_woh[EMBED * EMBED];

// ---------------------------------------------------------------------------
// helpers
// ---------------------------------------------------------------------------
__device__ __forceinline__ void mma_f16(float d[4], const unsigned a[4], const unsigned b[2]) {
    asm volatile(
        "mma.sync.aligned.m16n8k16.row.col.f32.f16.f16.f32 "
        "{%0,%1,%2,%3},{%4,%5,%6,%7},{%8,%9},{%0,%1,%2,%3};"
        : "+f"(d[0]), "+f"(d[1]), "+f"(d[2]), "+f"(d[3])
        : "r"(a[0]), "r"(a[1]), "r"(a[2]), "r"(a[3]), "r"(b[0]), "r"(b[1]));
}

__device__ __forceinline__ void ldmatrix_x4(unsigned r[4], uint32_t addr) {
    asm volatile("ldmatrix.sync.aligned.m8n8.x4.shared.b16 {%0,%1,%2,%3}, [%4];"
                 : "=r"(r[0]), "=r"(r[1]), "=r"(r[2]), "=r"(r[3]) : "r"(addr));
}

__device__ __forceinline__ void ldmatrix_x4_t(unsigned r[4], uint32_t addr) {
    asm volatile("ldmatrix.sync.aligned.m8n8.x4.trans.shared.b16 {%0,%1,%2,%3}, [%4];"
                 : "=r"(r[0]), "=r"(r[1]), "=r"(r[2]), "=r"(r[3]) : "r"(addr));
}

__device__ __forceinline__ void cp_async16(uint32_t saddr, const void* gptr) {
    asm volatile("cp.async.cg.shared.global [%0], [%1], 16;" :: "r"(saddr), "l"(gptr));
}
#define CP_COMMIT() asm volatile("cp.async.commit_group;")
#define CP_WAIT(n)  asm volatile("cp.async.wait_group %0;" :: "n"(n))

__device__ __forceinline__ uint32_t smem_u32(const void* p) {
    return (uint32_t)__cvta_generic_to_shared(p);
}

__device__ __forceinline__ unsigned packh2(float a, float b) {
    __half2 h = __floats2half2_rn(a, b);
    return *(unsigned*)&h;
}

// ===========================================================================
// fp16 GEMM (round-12 proven body): 128x128 tile, BK=64, 8 warps, 3-stage,
// single barrier per chunk. Output float (Cf) or half (Ch).
// ===========================================================================
#define GEMM_SMEM_BYTES 98304

__device__ __forceinline__ void gemm_h_body(
    const __half* __restrict__ A, const __half* __restrict__ W,
    const float* __restrict__ bias, float* __restrict__ Cf, __half* __restrict__ Ch,
    float alpha, int bm, int bn, char* smem)
{
    const uint32_t sb = smem_u32(smem);
    const int tid  = threadIdx.x;
    const int lane = tid & 31;
    const int warp = tid >> 5;
    const int wm = warp & 3;
    const int wn = warp >> 2;

    float acc[2][8][4] = {};

    const __half* Abase = A + (size_t)bm * EMBED;
    const __half* Wbase = W + (size_t)bn * EMBED;

    auto stage = [&](int c) {
        uint32_t buf = sb + (uint32_t)(c % 3) * 32768;
        const __half* ga = Abase + c * 64;
        const __half* gb = Wbase + c * 64;
#pragma unroll
        for (int l = 0; l < 4; l++) {
            int idx = tid + l * 256;
            int r = idx >> 3;
            int s = idx & 7;
            uint32_t off = (uint32_t)(r * 128 + ((s ^ (r & 7)) << 4));
            cp_async16(buf + off,         ga + (size_t)r * EMBED + s * 8);
            cp_async16(buf + 16384 + off, gb + (size_t)r * EMBED + s * 8);
        }
        CP_COMMIT();
    };

    const int r8  = lane & 7;
    const int sub = lane >> 3;

    auto compute = [&](int buf) {
        uint32_t ab = sb + (uint32_t)buf * 32768;
        uint32_t bb = ab + 16384;
#pragma unroll
        for (int ks = 0; ks < 4; ks++) {
            unsigned af[2][4];
#pragma unroll
            for (int mt = 0; mt < 2; mt++) {
                int row = wm * 32 + mt * 16 + ((sub & 1) << 3) + r8;
                int cs  = ks * 2 + (sub >> 1);
                ldmatrix_x4(af[mt], ab + row * 128 + (((cs ^ (row & 7))) << 4));
            }
#pragma unroll
            for (int np = 0; np < 4; np++) {
                int row = wn * 64 + np * 16 + ((sub >> 1) << 3) + r8;
                int cs  = ks * 2 + (sub & 1);
                unsigned bf[4];
                ldmatrix_x4(bf, bb + row * 128 + (((cs ^ (row & 7))) << 4));
                unsigned b0[2] = {bf[0], bf[1]};
                unsigned b1[2] = {bf[2], bf[3]};
#pragma unroll
                for (int mt = 0; mt < 2; mt++) {
                    mma_f16(acc[mt][np * 2 + 0], af[mt], b0);
                    mma_f16(acc[mt][np * 2 + 1], af[mt], b1);
                }
            }
        }
    };

    stage(0);
    stage(1);
#pragma unroll 1
    for (int c = 0; c < 12; c++) {
        if (c < 11) { CP_WAIT(1); } else { CP_WAIT(0); }
        __syncthreads();
        if (c + 2 < 12) stage(c + 2);
        compute(c % 3);
    }

    const int g  = lane >> 2;
    const int tg = lane & 3;
#pragma unroll
    for (int mt = 0; mt < 2; mt++) {
        int m0 = bm + wm * 32 + mt * 16 + g;
#pragma unroll
        for (int nt = 0; nt < 8; nt++) {
            int n0 = bn + wn * 64 + nt * 8 + tg * 2;
            float2 bi = *(const float2*)&bias[n0];
            float o00 = alpha * (acc[mt][nt][0] + bi.x);
            float o01 = alpha * (acc[mt][nt][1] + bi.y);
            float o10 = alpha * (acc[mt][nt][2] + bi.x);
            float o11 = alpha * (acc[mt][nt][3] + bi.y);
            if (Ch) {
                *(__half2*)&Ch[(size_t)m0 * EMBED + n0] = __floats2half2_rn(o00, o01);
                *(__half2*)&Ch[(size_t)(m0 + 8) * EMBED + n0] = __floats2half2_rn(o10, o11);
            } else {
                *(float2*)&Cf[(size_t)m0 * EMBED + n0] = make_float2(o00, o01);
                *(float2*)&Cf[(size_t)(m0 + 8) * EMBED + n0] = make_float2(o10, o11);
            }
        }
    }
}

__global__ __launch_bounds__(256, 2) void gemm_qkv_h(
    const __half* __restrict__ x,
    const __half* __restrict__ wq, const __half* __restrict__ wk, const __half* __restrict__ wv,
    const float* __restrict__ bq, const float* __restrict__ bk, const float* __restrict__ bv,
    __half* __restrict__ qo, __half* __restrict__ ko, __half* __restrict__ vo)
{
    extern __shared__ char gsm[];
    int sel = blockIdx.x / 6;
    int bn  = (blockIdx.x % 6) * 128;
    int bm  = blockIdx.y * 128;
    const __half* W   = (sel == 0) ? wq : (sel == 1) ? wk : wv;
    const float* bias = (sel == 0) ? bq : (sel == 1) ? bk : bv;
    __half* C         = (sel == 0) ? qo : (sel == 1) ? ko : vo;
    float alpha       = (sel == 0) ? 0.125f : 1.0f;
    gemm_h_body(x, W, bias, nullptr, C, alpha, bm, bn, gsm);
}

__global__ __launch_bounds__(256, 2) void gemm_out_h(
    const __half* __restrict__ A, const __half* __restrict__ W,
    const float* __restrict__ bias, float* __restrict__ C)
{
    extern __shared__ char gsm[];
    gemm_h_body(A, W, bias, C, nullptr, 1.0f, blockIdx.y * 128, blockIdx.x * 128, gsm);
}

// ---------------------------------------------------------------------------
// prep: convert x and the 4 weight matrices to half
// ---------------------------------------------------------------------------
#define NX4 (M_ROWS * EMBED / 4)
#define NW4 (EMBED * EMBED / 4)

__global__ __launch_bounds__(256) void prep_h(
    const float4* __restrict__ x,
    const float4* __restrict__ wq, const float4* __restrict__ wk,
    const float4* __restrict__ wv, const float4* __restrict__ wo,
    uint2* __restrict__ xh,
    uint2* __restrict__ wqh, uint2* __restrict__ wkh,
    uint2* __restrict__ wvh, uint2* __restrict__ woh)
{
    int i = blockIdx.x * 256 + threadIdx.x;
    auto cv = [](float4 t) {
        __half2 h0 = __floats2half2_rn(t.x, t.y);
        __half2 h1 = __floats2half2_rn(t.z, t.w);
        uint2 o;
        o.x = *(unsigned*)&h0;
        o.y = *(unsigned*)&h1;
        return o;
    };
    if (i < NX4) xh[i] = cv(x[i]);
    if (i < NW4) {
        wqh[i] = cv(wq[i]);
        wkh[i] = cv(wk[i]);
        wvh[i] = cv(wv[i]);
        woh[i] = cv(wo[i]);
    }
}

// ===========================================================================
// Streaming fused attention (round-12 structure, bias reads hoisted off the
// exp critical path). Block = (128 q rows, head b), 8 warps; warp w owns
// q rows [w*16, w*16+16). 32-key chunks; K/V/bias triple-buffered; per chunk:
//   WAIT -> sync -> stage(ch+2) -> [bias LDS + bias+mask pre-add] -> S-mma
//   -> exp -> PV-mma.
// P stays in registers: S-accum fragment == next mma's A fragment.
// SMEM: Q 16K + K 3x4K + V 3x4K + bias 3x18K = 94K -> 2 CTAs/SM.
// ===========================================================================
#define CH 32
#define NCH (N_NODE / CH)          // 16
#define QB_OFF    0
#define KB_OFF    16384
#define VB_OFF    (KB_OFF + 3 * 4096)          // 28672
#define BIASB_OFF (VB_OFF + 3 * 4096)          // 40960
#define BIAS_LDB  144              // bytes per bias row (36 floats)
#define BIAS_BYTES (128 * BIAS_LDB)            // 18432
#define ATTN_SMEM_BYTES (BIASB_OFF + 3 * BIAS_BYTES)   // 96256

__global__ __launch_bounds__(256, 2) void attn_h(
    const __half* __restrict__ q, const __half* __restrict__ k,
    const __half* __restrict__ v, const float* __restrict__ bias,
    const float* __restrict__ amask, const unsigned char* __restrict__ pad,
    __half* __restrict__ outh)
{
    extern __shared__ char asm_[];
    const uint32_t sb = smem_u32(asm_);

    const int b = blockIdx.y;
    const int graph = b / NHEAD;
    const int head  = b % NHEAD;
    const int q0 = blockIdx.x * 128;
    const int tid  = threadIdx.x;
    const int lane = tid & 31;
    const int w    = tid >> 5;
    const int r8   = lane & 7;
    const int sub  = lane >> 3;
    const int g    = lane >> 2;
    const int tg   = lane & 3;

    const int qrow = w * 16 + g;
    const int qg = q0 + qrow;

    const float* bias_gbase = bias + ((size_t)b * N_NODE + q0) * N_NODE;

    // ---- stage K/V/bias for chunk ch into buffer ch%3 (one commit group) ----
    auto stage = [&](int ch) {
        uint32_t buf = (uint32_t)(ch % 3);
        {
            int r = tid >> 3, s = tid & 7;   // 32 rows x 8 segs
            uint32_t off = (uint32_t)(r * 128 + ((s ^ (r & 7)) << 4));
            const __half* gk = k + ((size_t)(ch * CH + r) * N_GRAPH + graph) * EMBED + head * HDIM + s * 8;
            const __half* gv = v + ((size_t)(ch * CH + r) * N_GRAPH + graph) * EMBED + head * HDIM + s * 8;
            cp_async16(sb + KB_OFF + buf * 4096 + off, gk);
            cp_async16(sb + VB_OFF + buf * 4096 + off, gv);
        }
#pragma unroll
        for (int l = 0; l < 4; l++) {
            int idx = tid + l * 256;     // 0..1023
            int r = idx >> 3, s = idx & 7;
            uint32_t dst = sb + BIASB_OFF + buf * BIAS_BYTES + (uint32_t)(r * BIAS_LDB + s * 16);
            const float* src = bias_gbase + (size_t)r * N_NODE + ch * CH + s * 4;
            cp_async16(dst, src);
        }
        CP_COMMIT();
    };

    // ---- stage Q (128 rows x 64 halves); folded into chunk 0's commit group ----
    {
#pragma unroll
        for (int l = 0; l < 4; l++) {
            int idx = tid + l * 256;     // 0..1023
            int r = idx >> 3, s = idx & 7;
            uint32_t off = (uint32_t)(r * 128 + ((s ^ (r & 7)) << 4));
            const __half* src = q + ((size_t)(q0 + r) * N_GRAPH + graph) * EMBED + head * HDIM + s * 8;
            cp_async16(sb + QB_OFF + off, src);
        }
        // no commit: stage(0) commits Q together with chunk 0
    }
    stage(0);
    stage(1);

    float psum0 = 0.f, psum8 = 0.f;
    float oacc[8][4] = {};

#pragma unroll 1
    for (int ch = 0; ch < NCH; ch++) {
        const int buf = ch % 3;

        // ---- prefetch mask + pad (independent of staged data) ----
        float2 mk0[4], mk1[4];
        uchar2 pd[4];
        {
            const uchar2* pp = (const uchar2*)&pad[graph * N_NODE + ch * CH];
#pragma unroll
            for (int nt = 0; nt < 4; nt++) {
                int kg = ch * CH + nt * 8 + tg * 2;
                mk0[nt] = *(const float2*)&amask[(size_t)qg * N_NODE + kg];
                mk1[nt] = *(const float2*)&amask[(size_t)(qg + 8) * N_NODE + kg];
                pd[nt] = pp[nt * 4 + tg];
            }
        }

        if (ch < NCH - 1) { CP_WAIT(1); } else { CP_WAIT(0); }
        __syncthreads();   // chunk ch visible; all warps past compute(ch-1)

        if (ch + 2 < NCH) stage(ch + 2);   // writes buffer (ch-1)%3 — safe

        const uint32_t kbuf = sb + KB_OFF + (uint32_t)buf * 4096;
        const uint32_t vbuf = sb + VB_OFF + (uint32_t)buf * 4096;
        const float* bbuf = (const float*)(asm_ + BIASB_OFF + buf * BIAS_BYTES);

        // ---- hoisted bias loads + bias(+)mask pre-add (overlaps S-mma) ----
        float2 bm0[4], bm1[4];
#pragma unroll
        for (int nt = 0; nt < 4; nt++) {
            float2 bi0 = *(const float2*)&bbuf[qrow * 36 + nt * 8 + tg * 2];
            float2 bi1 = *(const float2*)&bbuf[(qrow + 8) * 36 + nt * 8 + tg * 2];
            bm0[nt] = make_float2(bi0.x + mk0[nt].x, bi0.y + mk0[nt].y);
            bm1[nt] = make_float2(bi1.x + mk1[nt].x, bi1.y + mk1[nt].y);
        }

        // ---- S = Q K^T : warp tile 16q x 32k, fp16 mma ----
        float sacc[4][4] = {};
#pragma unroll
        for (int ks = 0; ks < 4; ks++) {
            unsigned af[4];
            {
                int row = w * 16 + ((sub & 1) << 3) + r8;
                int cs  = ks * 2 + (sub >> 1);
                ldmatrix_x4(af, sb + QB_OFF + row * 128 + (((cs ^ (row & 7))) << 4));
            }
#pragma unroll
            for (int np = 0; np < 2; np++) {
                int row = np * 16 + ((sub >> 1) << 3) + r8;
                int cs  = ks * 2 + (sub & 1);
                unsigned bf[4];
                ldmatrix_x4(bf, kbuf + row * 128 + (((cs ^ (row & 7))) << 4));
                unsigned b0[2] = {bf[0], bf[1]};
                unsigned b1[2] = {bf[2], bf[3]};
                mma_f16(sacc[np * 2 + 0], af, b0);
                mma_f16(sacc[np * 2 + 1], af, b1);
            }
        }

        // ---- exp(S + (bias+mask)) ----
        float e[4][4];
#pragma unroll
        for (int nt = 0; nt < 4; nt++) {
            bool p0 = pd[nt].x, p1 = pd[nt].y;
            e[nt][0] = p0 ? 0.f : __expf(sacc[nt][0] + bm0[nt].x);
            e[nt][1] = p1 ? 0.f : __expf(sacc[nt][1] + bm0[nt].y);
            e[nt][2] = p0 ? 0.f : __expf(sacc[nt][2] + bm1[nt].x);
            e[nt][3] = p1 ? 0.f : __expf(sacc[nt][3] + bm1[nt].y);
            psum0 += e[nt][0] + e[nt][1];
            psum8 += e[nt][2] + e[nt][3];
        }

        // ---- O += P V : P packs directly into A fragments (registers only) ----
#pragma unroll
        for (int kk = 0; kk < 2; kk++) {
            unsigned pa[4];
            pa[0] = packh2(e[kk * 2][0], e[kk * 2][1]);
            pa[1] = packh2(e[kk * 2][2], e[kk * 2][3]);
            pa[2] = packh2(e[kk * 2 + 1][0], e[kk * 2 + 1][1]);
            pa[3] = packh2(e[kk * 2 + 1][2], e[kk * 2 + 1][3]);
#pragma unroll
            for (int nn = 0; nn < 4; nn++) {
                int row = kk * 16 + ((sub & 1) << 3) + r8;     // key row
                int seg = nn * 2 + (sub >> 1);                 // d segment
                unsigned vf[4];
                ldmatrix_x4_t(vf, vbuf + row * 128 + (((seg ^ (row & 7))) << 4));
                unsigned b0[2] = {vf[0], vf[1]};
                unsigned b1[2] = {vf[2], vf[3]};
                mma_f16(oacc[nn * 2 + 0], pa, b0);
                mma_f16(oacc[nn * 2 + 1], pa, b1);
            }
        }
    }

    // ---- normalize + write half (node, graph, embed) ----
    psum0 += __shfl_xor_sync(0xffffffffu, psum0, 1);
    psum0 += __shfl_xor_sync(0xffffffffu, psum0, 2);
    psum8 += __shfl_xor_sync(0xffffffffu, psum8, 1);
    psum8 += __shfl_xor_sync(0xffffffffu, psum8, 2);
    float inv0 = 1.0f / psum0;
    float inv8 = 1.0f / psum8;
    int node = q0 + qrow;
#pragma unroll
    for (int nt = 0; nt < 8; nt++) {
        int d = nt * 8 + tg * 2;
        *(__half2*)&outh[((size_t)node * N_GRAPH + graph) * EMBED + head * HDIM + d] =
            __floats2half2_rn(oacc[nt][0] * inv0, oacc[nt][1] * inv0);
        *(__half2*)&outh[((size_t)(node + 8) * N_GRAPH + graph) * EMBED + head * HDIM + d] =
            __floats2half2_rn(oacc[nt][2] * inv8, oacc[nt][3] * inv8);
    }
}

// ---------------------------------------------------------------------------
extern "C" void kernel_launch(void* const* d_in, const int* in_sizes, int n_in,
                              void* d_out, int out_size)
{
    const float* x     = (const float*)d_in[0];
    const float* bias  = (const float*)d_in[1];
    const float* amask = (const float*)d_in[2];
    const unsigned char* pad = (const unsigned char*)d_in[3];
    const float* wq = (const float*)d_in[4];
    const float* bq = (const float*)d_in[5];
    const float* wk = (const float*)d_in[6];
    const float* bk = (const float*)d_in[7];
    const float* wv = (const float*)d_in[8];
    const float* bv = (const float*)d_in[9];
    const float* wo = (const float*)d_in[10];
    const float* bo = (const float*)d_in[11];
    float* out = (float*)d_out;

    __half *qhp, *khp, *vhp, *ahp, *xhp, *wqhp, *wkhp, *wvhp, *wohp;
    cudaGetSymbolAddress((void**)&qhp, g_qh);
    cudaGetSymbolAddress((void**)&khp, g_kh);
    cudaGetSymbolAddress((void**)&vhp, g_vh);
    cudaGetSymbolAddress((void**)&ahp, g_ah);
    cudaGetSymbolAddress((void**)&xhp, g_xh);
    cudaGetSymbolAddress((void**)&wqhp, g_wqh);
    cudaGetSymbolAddress((void**)&wkhp, g_wkh);
    cudaGetSymbolAddress((void**)&wvhp, g_wvh);
    cudaGetSymbolAddress((void**)&wohp, g_woh);

    cudaFuncSetAttribute(gemm_qkv_h, cudaFuncAttributeMaxDynamicSharedMemorySize, GEMM_SMEM_BYTES);
    cudaFuncSetAttribute(gemm_out_h, cudaFuncAttributeMaxDynamicSharedMemorySize, GEMM_SMEM_BYTES);
    cudaFuncSetAttribute(attn_h, cudaFuncAttributeMaxDynamicSharedMemorySize, ATTN_SMEM_BYTES);

    prep_h<<<NX4 / 256, 256>>>(
        (const float4*)x, (const float4*)wq, (const float4*)wk,
        (const float4*)wv, (const float4*)wo,
        (uint2*)xhp, (uint2*)wqhp, (uint2*)wkhp, (uint2*)wvhp, (uint2*)wohp);

    dim3 qkvgrid(18, M_ROWS / 128);   // (18, 64)
    gemm_qkv_h<<<qkvgrid, 256, GEMM_SMEM_BYTES>>>(xhp, wqhp, wkhp, wvhp, bq, bk, bv, qhp, khp, vhp);

    dim3 agrid(N_NODE / 128, N_GRAPH * NHEAD);  // (4, 192)
    attn_h<<<agrid, 256, ATTN_SMEM_BYTES>>>(qhp, khp, vhp, bias, amask, pad, ahp);

    dim3 ogrid(EMBED / 128, M_ROWS / 128);      // (6, 64)
    gemm_out_h<<<ogrid, 256, GEMM_SMEM_BYTES>>>(ahp, wohp, bo, out);
}

// round 16
// speedup vs baseline: 1.1304x; 1.0994x over previous
#include <cuda_runtime.h>
#include <cuda_fp16.h>
#include <math.h>
#include <stdint.h>

#define N_NODE   512
#define N_GRAPH  16
#define EMBED    768
#define NHEAD    12
#define HDIM     64
#define M_ROWS   (N_NODE * N_GRAPH)   // 8192

// Scratch (device globals — no allocation allowed)
__device__ __half g_qh[M_ROWS * EMBED];
__device__ __half g_kh[M_ROWS * EMBED];
__device__ __half g_vh[M_ROWS * EMBED];
__device__ __half g_ah[M_ROWS * EMBED];        // attn output (half)
__device__ __half g_xh[M_ROWS * EMBED];        // x converted to half
__device__ __half g_wqh[EMBED * EMBED];
__device__ __half g_wkh[EMBED * EMBED];
__device__ __half g_wvh[EMBED * EMBED];
__device__ __half g_woh[EMBED * EMBED];

// ---------------------------------------------------------------------------
// helpers
// ---------------------------------------------------------------------------
__device__ __forceinline__ void mma_f16(float d[4], const unsigned a[4], const unsigned b[2]) {
    asm volatile(
        "mma.sync.aligned.m16n8k16.row.col.f32.f16.f16.f32 "
        "{%0,%1,%2,%3},{%4,%5,%6,%7},{%8,%9},{%0,%1,%2,%3};"
        : "+f"(d[0]), "+f"(d[1]), "+f"(d[2]), "+f"(d[3])
        : "r"(a[0]), "r"(a[1]), "r"(a[2]), "r"(a[3]), "r"(b[0]), "r"(b[1]));
}

__device__ __forceinline__ void ldmatrix_x4(unsigned r[4], uint32_t addr) {
    asm volatile("ldmatrix.sync.aligned.m8n8.x4.shared.b16 {%0,%1,%2,%3}, [%4];"
                 : "=r"(r[0]), "=r"(r[1]), "=r"(r[2]), "=r"(r[3]) : "r"(addr));
}

__device__ __forceinline__ void ldmatrix_x4_t(unsigned r[4], uint32_t addr) {
    asm volatile("ldmatrix.sync.aligned.m8n8.x4.trans.shared.b16 {%0,%1,%2,%3}, [%4];"
                 : "=r"(r[0]), "=r"(r[1]), "=r"(r[2]), "=r"(r[3]) : "r"(addr));
}

__device__ __forceinline__ void cp_async16(uint32_t saddr, const void* gptr) {
    asm volatile("cp.async.cg.shared.global [%0], [%1], 16;" :: "r"(saddr), "l"(gptr));
}
#define CP_COMMIT() asm volatile("cp.async.commit_group;")
#define CP_WAIT(n)  asm volatile("cp.async.wait_group %0;" :: "n"(n))

__device__ __forceinline__ uint32_t smem_u32(const void* p) {
    return (uint32_t)__cvta_generic_to_shared(p);
}

__device__ __forceinline__ unsigned packh2(float a, float b) {
    __half2 h = __floats2half2_rn(a, b);
    return *(unsigned*)&h;
}

// ===========================================================================
// fp16 GEMM (round-12 proven body): 128x128 tile, BK=64, 8 warps, 3-stage,
// single barrier per chunk. Output float (Cf) or half (Ch).
// ===========================================================================
#define GEMM_SMEM_BYTES 98304

__device__ __forceinline__ void gemm_h_body(
    const __half* __restrict__ A, const __half* __restrict__ W,
    const float* __restrict__ bias, float* __restrict__ Cf, __half* __restrict__ Ch,
    float alpha, int bm, int bn, char* smem)
{
    const uint32_t sb = smem_u32(smem);
    const int tid  = threadIdx.x;
    const int lane = tid & 31;
    const int warp = tid >> 5;
    const int wm = warp & 3;
    const int wn = warp >> 2;

    float acc[2][8][4] = {};

    const __half* Abase = A + (size_t)bm * EMBED;
    const __half* Wbase = W + (size_t)bn * EMBED;

    auto stage = [&](int c) {
        uint32_t buf = sb + (uint32_t)(c % 3) * 32768;
        const __half* ga = Abase + c * 64;
        const __half* gb = Wbase + c * 64;
#pragma unroll
        for (int l = 0; l < 4; l++) {
            int idx = tid + l * 256;
            int r = idx >> 3;
            int s = idx & 7;
            uint32_t off = (uint32_t)(r * 128 + ((s ^ (r & 7)) << 4));
            cp_async16(buf + off,         ga + (size_t)r * EMBED + s * 8);
            cp_async16(buf + 16384 + off, gb + (size_t)r * EMBED + s * 8);
        }
        CP_COMMIT();
    };

    const int r8  = lane & 7;
    const int sub = lane >> 3;

    auto compute = [&](int buf) {
        uint32_t ab = sb + (uint32_t)buf * 32768;
        uint32_t bb = ab + 16384;
#pragma unroll
        for (int ks = 0; ks < 4; ks++) {
            unsigned af[2][4];
#pragma unroll
            for (int mt = 0; mt < 2; mt++) {
                int row = wm * 32 + mt * 16 + ((sub & 1) << 3) + r8;
                int cs  = ks * 2 + (sub >> 1);
                ldmatrix_x4(af[mt], ab + row * 128 + (((cs ^ (row & 7))) << 4));
            }
#pragma unroll
            for (int np = 0; np < 4; np++) {
                int row = wn * 64 + np * 16 + ((sub >> 1) << 3) + r8;
                int cs  = ks * 2 + (sub & 1);
                unsigned bf[4];
                ldmatrix_x4(bf, bb + row * 128 + (((cs ^ (row & 7))) << 4));
                unsigned b0[2] = {bf[0], bf[1]};
                unsigned b1[2] = {bf[2], bf[3]};
#pragma unroll
                for (int mt = 0; mt < 2; mt++) {
                    mma_f16(acc[mt][np * 2 + 0], af[mt], b0);
                    mma_f16(acc[mt][np * 2 + 1], af[mt], b1);
                }
            }
        }
    };

    stage(0);
    stage(1);
#pragma unroll 1
    for (int c = 0; c < 12; c++) {
        if (c < 11) { CP_WAIT(1); } else { CP_WAIT(0); }
        __syncthreads();
        if (c + 2 < 12) stage(c + 2);
        compute(c % 3);
    }

    const int g  = lane >> 2;
    const int tg = lane & 3;
#pragma unroll
    for (int mt = 0; mt < 2; mt++) {
        int m0 = bm + wm * 32 + mt * 16 + g;
#pragma unroll
        for (int nt = 0; nt < 8; nt++) {
            int n0 = bn + wn * 64 + nt * 8 + tg * 2;
            float2 bi = *(const float2*)&bias[n0];
            float o00 = alpha * (acc[mt][nt][0] + bi.x);
            float o01 = alpha * (acc[mt][nt][1] + bi.y);
            float o10 = alpha * (acc[mt][nt][2] + bi.x);
            float o11 = alpha * (acc[mt][nt][3] + bi.y);
            if (Ch) {
                *(__half2*)&Ch[(size_t)m0 * EMBED + n0] = __floats2half2_rn(o00, o01);
                *(__half2*)&Ch[(size_t)(m0 + 8) * EMBED + n0] = __floats2half2_rn(o10, o11);
            } else {
                *(float2*)&Cf[(size_t)m0 * EMBED + n0] = make_float2(o00, o01);
                *(float2*)&Cf[(size_t)(m0 + 8) * EMBED + n0] = make_float2(o10, o11);
            }
        }
    }
}

__global__ __launch_bounds__(256, 2) void gemm_qkv_h(
    const __half* __restrict__ x,
    const __half* __restrict__ wq, const __half* __restrict__ wk, const __half* __restrict__ wv,
    const float* __restrict__ bq, const float* __restrict__ bk, const float* __restrict__ bv,
    __half* __restrict__ qo, __half* __restrict__ ko, __half* __restrict__ vo)
{
    extern __shared__ char gsm[];
    int sel = blockIdx.x / 6;
    int bn  = (blockIdx.x % 6) * 128;
    int bm  = blockIdx.y * 128;
    const __half* W   = (sel == 0) ? wq : (sel == 1) ? wk : wv;
    const float* bias = (sel == 0) ? bq : (sel == 1) ? bk : bv;
    __half* C         = (sel == 0) ? qo : (sel == 1) ? ko : vo;
    float alpha       = (sel == 0) ? 0.125f : 1.0f;
    gemm_h_body(x, W, bias, nullptr, C, alpha, bm, bn, gsm);
}

__global__ __launch_bounds__(256, 2) void gemm_out_h(
    const __half* __restrict__ A, const __half* __restrict__ W,
    const float* __restrict__ bias, float* __restrict__ C)
{
    extern __shared__ char gsm[];
    gemm_h_body(A, W, bias, C, nullptr, 1.0f, blockIdx.y * 128, blockIdx.x * 128, gsm);
}

// ---------------------------------------------------------------------------
// prep: convert x and the 4 weight matrices to half
// ---------------------------------------------------------------------------
#define NX4 (M_ROWS * EMBED / 4)
#define NW4 (EMBED * EMBED / 4)

__global__ __launch_bounds__(256) void prep_h(
    const float4* __restrict__ x,
    const float4* __restrict__ wq, const float4* __restrict__ wk,
    const float4* __restrict__ wv, const float4* __restrict__ wo,
    uint2* __restrict__ xh,
    uint2* __restrict__ wqh, uint2* __restrict__ wkh,
    uint2* __restrict__ wvh, uint2* __restrict__ woh)
{
    int i = blockIdx.x * 256 + threadIdx.x;
    auto cv = [](float4 t) {
        __half2 h0 = __floats2half2_rn(t.x, t.y);
        __half2 h1 = __floats2half2_rn(t.z, t.w);
        uint2 o;
        o.x = *(unsigned*)&h0;
        o.y = *(unsigned*)&h1;
        return o;
    };
    if (i < NX4) xh[i] = cv(x[i]);
    if (i < NW4) {
        wqh[i] = cv(wq[i]);
        wkh[i] = cv(wk[i]);
        wvh[i] = cv(wv[i]);
        woh[i] = cv(wo[i]);
    }
}

// ===========================================================================
// Streaming fused attention — CTA = 64 q-rows x head, 4 warps (128 threads),
// 4 CTAs/SM: same 16 warps/SM as round 12 but 4 independent barrier domains.
// Per-warp work identical to round-12 shape: warp tile 16q x 32k, CH=32,
// K/V/bias 3-stage, single barrier per chunk:
//   WAIT -> sync -> stage(ch+2) -> [bias+mask pre-add] -> S-mma -> exp -> PV.
// Q ldmatrix'd once into registers (staged via bias buffer area).
// SMEM: K 3x4K + V 3x4K + bias 3x9K = 51K -> 4 CTAs/SM (204KB).
// ===========================================================================
#define CH 32
#define NCH (N_NODE / CH)          // 16
#define AQROWS 64
#define ATHREADS 128
#define KB_OFF    0
#define VB_OFF    (3 * 4096)                   // 12288
#define BIASB_OFF (2 * 3 * 4096)               // 24576
#define BIAS_LDB  144              // bytes per bias row (36 floats)
#define BIAS_BYTES (AQROWS * BIAS_LDB)         // 9216
#define ATTN_SMEM_BYTES (BIASB_OFF + 3 * BIAS_BYTES)   // 52224

__global__ __launch_bounds__(ATHREADS, 4) void attn_h(
    const __half* __restrict__ q, const __half* __restrict__ k,
    const __half* __restrict__ v, const float* __restrict__ bias,
    const float* __restrict__ amask, const unsigned char* __restrict__ pad,
    __half* __restrict__ outh)
{
    extern __shared__ char asm_[];
    const uint32_t sb = smem_u32(asm_);

    const int b = blockIdx.y;
    const int graph = b / NHEAD;
    const int head  = b % NHEAD;
    const int q0 = blockIdx.x * AQROWS;
    const int tid  = threadIdx.x;
    const int lane = tid & 31;
    const int w    = tid >> 5;      // 0..3
    const int r8   = lane & 7;
    const int sub  = lane >> 3;
    const int g    = lane >> 2;
    const int tg   = lane & 3;

    const int qrow = w * 16 + g;    // local q row (0..63)
    const int qg = q0 + qrow;

    const float* bias_gbase = bias + ((size_t)b * N_NODE + q0) * N_NODE;

    // ---- stage K/V/bias for chunk ch into buffer ch%3 (one commit group) ----
    auto stage = [&](int ch) {
        uint32_t buf = (uint32_t)(ch % 3);
#pragma unroll
        for (int l = 0; l < 2; l++) {
            int idx = tid + l * ATHREADS;    // 0..255 (32 rows x 8 segs)
            int r = idx >> 3, s = idx & 7;
            uint32_t off = (uint32_t)(r * 128 + ((s ^ (r & 7)) << 4));
            const __half* gk = k + ((size_t)(ch * CH + r) * N_GRAPH + graph) * EMBED + head * HDIM + s * 8;
            const __half* gv = v + ((size_t)(ch * CH + r) * N_GRAPH + graph) * EMBED + head * HDIM + s * 8;
            cp_async16(sb + KB_OFF + buf * 4096 + off, gk);
            cp_async16(sb + VB_OFF + buf * 4096 + off, gv);
        }
#pragma unroll
        for (int l = 0; l < 4; l++) {
            int idx = tid + l * ATHREADS;    // 0..511 (64 rows x 8 segs)
            int r = idx >> 3, s = idx & 7;
            uint32_t dst = sb + BIASB_OFF + buf * BIAS_BYTES + (uint32_t)(r * BIAS_LDB + s * 16);
            const float* src = bias_gbase + (size_t)r * N_NODE + ch * CH + s * 4;
            cp_async16(dst, src);
        }
        CP_COMMIT();
    };

    // ---- Q fragments: stage once into bias area, ldmatrix into registers ----
    unsigned afq[4][4];
    {
#pragma unroll
        for (int l = 0; l < 4; l++) {
            int idx = tid + l * ATHREADS;    // 0..511 (64 rows x 8 segs)
            int r = idx >> 3, s = idx & 7;
            uint32_t off = (uint32_t)(r * 128 + ((s ^ (r & 7)) << 4));
            const __half* src = q + ((size_t)(q0 + r) * N_GRAPH + graph) * EMBED + head * HDIM + s * 8;
            cp_async16(sb + BIASB_OFF + off, src);
        }
        CP_COMMIT();
        CP_WAIT(0);
        __syncthreads();
#pragma unroll
        for (int ks = 0; ks < 4; ks++) {
            int row = w * 16 + ((sub & 1) << 3) + r8;
            int cs  = ks * 2 + (sub >> 1);
            ldmatrix_x4(afq[ks], sb + BIASB_OFF + row * 128 + (((cs ^ (row & 7))) << 4));
        }
        __syncthreads();   // Q temp reads complete before bias staging overwrites
    }
    stage(0);
    stage(1);

    float psum0 = 0.f, psum8 = 0.f;
    float oacc[8][4] = {};

#pragma unroll 1
    for (int ch = 0; ch < NCH; ch++) {
        const int buf = ch % 3;

        // ---- prefetch mask + pad (independent of staged data) ----
        float2 mk0[4], mk1[4];
        uchar2 pd[4];
        {
            const uchar2* pp = (const uchar2*)&pad[graph * N_NODE + ch * CH];
#pragma unroll
            for (int nt = 0; nt < 4; nt++) {
                int kg = ch * CH + nt * 8 + tg * 2;
                mk0[nt] = *(const float2*)&amask[(size_t)qg * N_NODE + kg];
                mk1[nt] = *(const float2*)&amask[(size_t)(qg + 8) * N_NODE + kg];
                pd[nt] = pp[nt * 4 + tg];
            }
        }

        if (ch < NCH - 1) { CP_WAIT(1); } else { CP_WAIT(0); }
        __syncthreads();   // chunk ch visible; all warps past compute(ch-1)

        if (ch + 2 < NCH) stage(ch + 2);   // writes buffer (ch-1)%3 — safe

        const uint32_t kbuf = sb + KB_OFF + (uint32_t)buf * 4096;
        const uint32_t vbuf = sb + VB_OFF + (uint32_t)buf * 4096;
        const float* bbuf = (const float*)(asm_ + BIASB_OFF + buf * BIAS_BYTES);

        // ---- hoisted bias loads + bias(+)mask pre-add (overlaps S-mma) ----
        float2 bm0[4], bm1[4];
#pragma unroll
        for (int nt = 0; nt < 4; nt++) {
            float2 bi0 = *(const float2*)&bbuf[qrow * 36 + nt * 8 + tg * 2];
            float2 bi1 = *(const float2*)&bbuf[(qrow + 8) * 36 + nt * 8 + tg * 2];
            bm0[nt] = make_float2(bi0.x + mk0[nt].x, bi0.y + mk0[nt].y);
            bm1[nt] = make_float2(bi1.x + mk1[nt].x, bi1.y + mk1[nt].y);
        }

        // ---- S = Q K^T : warp tile 16q x 32k, fp16 mma (A from registers) ----
        float sacc[4][4] = {};
#pragma unroll
        for (int ks = 0; ks < 4; ks++) {
#pragma unroll
            for (int np = 0; np < 2; np++) {
                int row = np * 16 + ((sub >> 1) << 3) + r8;
                int cs  = ks * 2 + (sub & 1);
                unsigned bf[4];
                ldmatrix_x4(bf, kbuf + row * 128 + (((cs ^ (row & 7))) << 4));
                unsigned b0[2] = {bf[0], bf[1]};
                unsigned b1[2] = {bf[2], bf[3]};
                mma_f16(sacc[np * 2 + 0], afq[ks], b0);
                mma_f16(sacc[np * 2 + 1], afq[ks], b1);
            }
        }

        // ---- exp(S + (bias+mask)) ----
        float e[4][4];
#pragma unroll
        for (int nt = 0; nt < 4; nt++) {
            bool p0 = pd[nt].x, p1 = pd[nt].y;
            e[nt][0] = p0 ? 0.f : __expf(sacc[nt][0] + bm0[nt].x);
            e[nt][1] = p1 ? 0.f : __expf(sacc[nt][1] + bm0[nt].y);
            e[nt][2] = p0 ? 0.f : __expf(sacc[nt][2] + bm1[nt].x);
            e[nt][3] = p1 ? 0.f : __expf(sacc[nt][3] + bm1[nt].y);
            psum0 += e[nt][0] + e[nt][1];
            psum8 += e[nt][2] + e[nt][3];
        }

        // ---- O += P V : P packs directly into A fragments (registers only) ----
#pragma unroll
        for (int kk = 0; kk < 2; kk++) {
            unsigned pa[4];
            pa[0] = packh2(e[kk * 2][0], e[kk * 2][1]);
            pa[1] = packh2(e[kk * 2][2], e[kk * 2][3]);
            pa[2] = packh2(e[kk * 2 + 1][0], e[kk * 2 + 1][1]);
            pa[3] = packh2(e[kk * 2 + 1][2], e[kk * 2 + 1][3]);
#pragma unroll
            for (int nn = 0; nn < 4; nn++) {
                int row = kk * 16 + ((sub & 1) << 3) + r8;     // key row
                int seg = nn * 2 + (sub >> 1);                 // d segment
                unsigned vf[4];
                ldmatrix_x4_t(vf, vbuf + row * 128 + (((seg ^ (row & 7))) << 4));
                unsigned b0[2] = {vf[0], vf[1]};
                unsigned b1[2] = {vf[2], vf[3]};
                mma_f16(oacc[nn * 2 + 0], pa, b0);
                mma_f16(oacc[nn * 2 + 1], pa, b1);
            }
        }
    }

    // ---- normalize + write half (node, graph, embed) ----
    psum0 += __shfl_xor_sync(0xffffffffu, psum0, 1);
    psum0 += __shfl_xor_sync(0xffffffffu, psum0, 2);
    psum8 += __shfl_xor_sync(0xffffffffu, psum8, 1);
    psum8 += __shfl_xor_sync(0xffffffffu, psum8, 2);
    float inv0 = 1.0f / psum0;
    float inv8 = 1.0f / psum8;
    int node = q0 + qrow;
#pragma unroll
    for (int nt = 0; nt < 8; nt++) {
        int d = nt * 8 + tg * 2;
        *(__half2*)&outh[((size_t)node * N_GRAPH + graph) * EMBED + head * HDIM + d] =
            __floats2half2_rn(oacc[nt][0] * inv0, oacc[nt][1] * inv0);
        *(__half2*)&outh[((size_t)(node + 8) * N_GRAPH + graph) * EMBED + head * HDIM + d] =
            __floats2half2_rn(oacc[nt][2] * inv8, oacc[nt][3] * inv8);
    }
}

// ---------------------------------------------------------------------------
extern "C" void kernel_launch(void* const* d_in, const int* in_sizes, int n_in,
                              void* d_out, int out_size)
{
    const float* x     = (const float*)d_in[0];
    const float* bias  = (const float*)d_in[1];
    const float* amask = (const float*)d_in[2];
    const unsigned char* pad = (const unsigned char*)d_in[3];
    const float* wq = (const float*)d_in[4];
    const float* bq = (const float*)d_in[5];
    const float* wk = (const float*)d_in[6];
    const float* bk = (const float*)d_in[7];
    const float* wv = (const float*)d_in[8];
    const float* bv = (const float*)d_in[9];
    const float* wo = (const float*)d_in[10];
    const float* bo = (const float*)d_in[11];
    float* out = (float*)d_out;

    __half *qhp, *khp, *vhp, *ahp, *xhp, *wqhp, *wkhp, *wvhp, *wohp;
    cudaGetSymbolAddress((void**)&qhp, g_qh);
    cudaGetSymbolAddress((void**)&khp, g_kh);
    cudaGetSymbolAddress((void**)&vhp, g_vh);
    cudaGetSymbolAddress((void**)&ahp, g_ah);
    cudaGetSymbolAddress((void**)&xhp, g_xh);
    cudaGetSymbolAddress((void**)&wqhp, g_wqh);
    cudaGetSymbolAddress((void**)&wkhp, g_wkh);
    cudaGetSymbolAddress((void**)&wvhp, g_wvh);
    cudaGetSymbolAddress((void**)&wohp, g_woh);

    cudaFuncSetAttribute(gemm_qkv_h, cudaFuncAttributeMaxDynamicSharedMemorySize, GEMM_SMEM_BYTES);
    cudaFuncSetAttribute(gemm_out_h, cudaFuncAttributeMaxDynamicSharedMemorySize, GEMM_SMEM_BYTES);
    cudaFuncSetAttribute(attn_h, cudaFuncAttributeMaxDynamicSharedMemorySize, ATTN_SMEM_BYTES);

    prep_h<<<NX4 / 256, 256>>>(
        (const float4*)x, (const float4*)wq, (const float4*)wk,
        (const float4*)wv, (const float4*)wo,
        (uint2*)xhp, (uint2*)wqhp, (uint2*)wkhp, (uint2*)wvhp, (uint2*)wohp);

    dim3 qkvgrid(18, M_ROWS / 128);   // (18, 64)
    gemm_qkv_h<<<qkvgrid, 256, GEMM_SMEM_BYTES>>>(xhp, wqhp, wkhp, wvhp, bq, bk, bv, qhp, khp, vhp);

    dim3 agrid(N_NODE / AQROWS, N_GRAPH * NHEAD);  // (8, 192)
    attn_h<<<agrid, ATHREADS, ATTN_SMEM_BYTES>>>(qhp, khp, vhp, bias, amask, pad, ahp);

    dim3 ogrid(EMBED / 128, M_ROWS / 128);      // (6, 64)
    gemm_out_h<<<ogrid, 256, GEMM_SMEM_BYTES>>>(ahp, wohp, bo, out);
}